// round 11
// baseline (speedup 1.0000x reference)
#include <cuda_runtime.h>
#include <cuda_fp16.h>
#include <cstdint>
#include <cstddef>

// Flash-attention-2 forward, fp16 tensor-core path (mma.sync.m16n8k16).
// R11: each warp now owns 32 query rows (two 16-row fragments), BM=128.
// Halves LDSM traffic per MMA (each K/V fragment feeds 4 MMAs instead of 2).
// K/V pre-converted to fp16 scratch; cp.async.cg double-buffered mainloop.

namespace {

constexpr int S  = 2048;
constexpr int D  = 64;
constexpr int BM = 128;  // query rows per CTA (4 warps x 32)
constexpr int BN = 64;   // keys per tile
constexpr int NT = S / BN;
constexpr int KST = 72;  // smem row stride in halves (144 B) -> conflict-free LDSM
constexpr int BH = 2 * 16;
constexpr size_t ELEMS = (size_t)BH * S * D;  // 4,194,304 per tensor

__device__ __half g_Kh[ELEMS];
__device__ __half g_Vh[ELEMS];

__global__ void __launch_bounds__(256)
cvt_kv(const float* __restrict__ K, const float* __restrict__ V) {
    const int i = blockIdx.x * blockDim.x + threadIdx.x;  // float4 index
    const int n4 = (int)(ELEMS / 4);
    if (i < n4) {
        float4 kv = ((const float4*)K)[i];
        float4 vv = ((const float4*)V)[i];
        __half2* kd = reinterpret_cast<__half2*>(g_Kh) + 2 * i;
        __half2* vd = reinterpret_cast<__half2*>(g_Vh) + 2 * i;
        kd[0] = __floats2half2_rn(kv.x, kv.y);
        kd[1] = __floats2half2_rn(kv.z, kv.w);
        vd[0] = __floats2half2_rn(vv.x, vv.y);
        vd[1] = __floats2half2_rn(vv.z, vv.w);
    }
}

__device__ __forceinline__ float ex2(float x) {
    float y;
    asm volatile("ex2.approx.ftz.f32 %0, %1;" : "=f"(y) : "f"(x));
    return y;
}

__device__ __forceinline__ uint32_t packh2(float a, float b) {
    __half2 h = __floats2half2_rn(a, b);
    return *reinterpret_cast<uint32_t*>(&h);
}

__device__ __forceinline__ void cp_async16(uint32_t dst, const void* src) {
    asm volatile("cp.async.cg.shared.global [%0], [%1], 16;" :: "r"(dst), "l"(src));
}

__device__ __forceinline__ void ldsm_x4(uint32_t& d0, uint32_t& d1, uint32_t& d2, uint32_t& d3,
                                        uint32_t addr) {
    asm volatile("ldmatrix.sync.aligned.m8n8.x4.shared.b16 {%0,%1,%2,%3}, [%4];"
                 : "=r"(d0), "=r"(d1), "=r"(d2), "=r"(d3) : "r"(addr));
}

__device__ __forceinline__ void ldsm_x4_t(uint32_t& d0, uint32_t& d1, uint32_t& d2, uint32_t& d3,
                                          uint32_t addr) {
    asm volatile("ldmatrix.sync.aligned.m8n8.x4.trans.shared.b16 {%0,%1,%2,%3}, [%4];"
                 : "=r"(d0), "=r"(d1), "=r"(d2), "=r"(d3) : "r"(addr));
}

__device__ __forceinline__ void mma16816(float* c,
                                         uint32_t a0, uint32_t a1, uint32_t a2, uint32_t a3,
                                         uint32_t b0, uint32_t b1) {
    asm volatile("mma.sync.aligned.m16n8k16.row.col.f32.f16.f16.f32 "
                 "{%0,%1,%2,%3}, {%4,%5,%6,%7}, {%8,%9}, {%0,%1,%2,%3};"
                 : "+f"(c[0]), "+f"(c[1]), "+f"(c[2]), "+f"(c[3])
                 : "r"(a0), "r"(a1), "r"(a2), "r"(a3), "r"(b0), "r"(b1));
}

__global__ void __launch_bounds__(128)
fa_fwd(const float* __restrict__ Qg, float* __restrict__ Og) {
    // double-buffered fp16 tiles
    __shared__ __align__(16) __half Ksh[2][BN * KST];
    __shared__ __align__(16) __half Vsh[2][BN * KST];

    const int bh    = blockIdx.y;
    const int mbase = blockIdx.x * BM;
    const float*  Qp = Qg   + (size_t)bh * S * D;
    const __half* Kp = g_Kh + (size_t)bh * S * D;
    const __half* Vp = g_Vh + (size_t)bh * S * D;
    float*        Op = Og   + (size_t)bh * S * D;

    const int tid  = threadIdx.x;
    const int warp = tid >> 5;
    const int lane = tid & 31;
    const int g    = lane >> 2;
    const int q    = lane & 3;
    const int wrow = mbase + warp * 32;  // this warp's 32-row block

    const float cs = 0.125f * 1.4426950408889634f;  // 1/sqrt(D) * log2(e)

    // ---- Q fragments (scaled fp16), two 16-row fragments per warp ----
    uint32_t qa[2][4][4];
#pragma unroll
    for (int f = 0; f < 2; ++f) {
        const int rr0 = wrow + f * 16 + g;
        const int rr1 = rr0 + 8;
#pragma unroll
        for (int kt = 0; kt < 4; ++kt) {
            const int c = kt * 16 + 2 * q;
            float2 t;
            t = *(const float2*)(Qp + (size_t)rr0 * D + c);
            qa[f][kt][0] = packh2(t.x * cs, t.y * cs);
            t = *(const float2*)(Qp + (size_t)rr1 * D + c);
            qa[f][kt][1] = packh2(t.x * cs, t.y * cs);
            t = *(const float2*)(Qp + (size_t)rr0 * D + c + 8);
            qa[f][kt][2] = packh2(t.x * cs, t.y * cs);
            t = *(const float2*)(Qp + (size_t)rr1 * D + c + 8);
            qa[f][kt][3] = packh2(t.x * cs, t.y * cs);
        }
    }

    float oacc[2][8][4];
#pragma unroll
    for (int f = 0; f < 2; ++f)
#pragma unroll
        for (int j = 0; j < 8; ++j)
#pragma unroll
            for (int k = 0; k < 4; ++k) oacc[f][j][k] = 0.f;

    const float NEGINF = -1e30f;
    float mr[2][2] = {{NEGINF, NEGINF}, {NEGINF, NEGINF}};
    float lr[2][2] = {{0.f, 0.f}, {0.f, 0.f}};

    uint32_t ks_base[2], vs_base[2];
    ks_base[0] = (uint32_t)__cvta_generic_to_shared(&Ksh[0][0]);
    ks_base[1] = (uint32_t)__cvta_generic_to_shared(&Ksh[1][0]);
    vs_base[0] = (uint32_t)__cvta_generic_to_shared(&Vsh[0][0]);
    vs_base[1] = (uint32_t)__cvta_generic_to_shared(&Vsh[1][0]);

    // cp.async tile issue: 64 rows x 128B per tensor = 512 chunks of 16B, 4/thread
    auto issue_tile = [&](int nt, int stage) {
        const __half* Kt = Kp + (size_t)nt * BN * D;
        const __half* Vt = Vp + (size_t)nt * BN * D;
#pragma unroll
        for (int i = 0; i < 4; ++i) {
            const int idx = tid + i * 128;
            const int row = idx >> 3;
            const int col = (idx & 7) * 8;  // halves
            const uint32_t off = 2u * (uint32_t)(row * KST + col);
            cp_async16(ks_base[stage] + off, Kt + row * D + col);
            cp_async16(vs_base[stage] + off, Vt + row * D + col);
        }
        asm volatile("cp.async.commit_group;");
    };

    // ldmatrix per-lane address components
    const int lj = lane >> 3, lr8 = lane & 7;
    const int krow = (lj & 2) * 4 + lr8;
    const int kcol = (lj & 1) * 8;
    const int vrow = (lj & 1) * 8 + lr8;
    const int vcol = (lj & 2) * 4;

    issue_tile(0, 0);

    for (int nt = 0; nt < NT; ++nt) {
        const int cur = nt & 1;

        asm volatile("cp.async.wait_group 0;");
        __syncthreads();

        if (nt + 1 < NT) issue_tile(nt + 1, cur ^ 1);

        // ---- S = (Q*cs) K^T : one K ldsm feeds 4 MMAs (2 frags x 2 n-halves)
        float sacc[2][8][4];
#pragma unroll
        for (int f = 0; f < 2; ++f)
#pragma unroll
            for (int j = 0; j < 8; ++j)
#pragma unroll
                for (int k = 0; k < 4; ++k) sacc[f][j][k] = 0.f;

#pragma unroll
        for (int np = 0; np < 4; ++np) {
#pragma unroll
            for (int kt = 0; kt < 4; ++kt) {
                uint32_t b0, b1, b2, b3;
                const uint32_t addr =
                    ks_base[cur] + 2u * (uint32_t)((np * 16 + krow) * KST + kt * 16 + kcol);
                ldsm_x4(b0, b1, b2, b3, addr);
#pragma unroll
                for (int f = 0; f < 2; ++f) {
                    mma16816(sacc[f][2 * np],
                             qa[f][kt][0], qa[f][kt][1], qa[f][kt][2], qa[f][kt][3], b0, b1);
                    mma16816(sacc[f][2 * np + 1],
                             qa[f][kt][0], qa[f][kt][1], qa[f][kt][2], qa[f][kt][3], b2, b3);
                }
            }
        }

        // ---- online softmax (base-2), per fragment ----
        uint32_t pa[2][8], pb[2][8];
#pragma unroll
        for (int f = 0; f < 2; ++f) {
            float mx0 = NEGINF, mx1 = NEGINF;
#pragma unroll
            for (int j = 0; j < 8; ++j) {
                mx0 = fmaxf(mx0, fmaxf(sacc[f][j][0], sacc[f][j][1]));
                mx1 = fmaxf(mx1, fmaxf(sacc[f][j][2], sacc[f][j][3]));
            }
            mx0 = fmaxf(mx0, __shfl_xor_sync(0xffffffffu, mx0, 1));
            mx0 = fmaxf(mx0, __shfl_xor_sync(0xffffffffu, mx0, 2));
            mx1 = fmaxf(mx1, __shfl_xor_sync(0xffffffffu, mx1, 1));
            mx1 = fmaxf(mx1, __shfl_xor_sync(0xffffffffu, mx1, 2));

            const float mn0 = fmaxf(mr[f][0], mx0);
            const float mn1 = fmaxf(mr[f][1], mx1);
            const float al0 = ex2(mr[f][0] - mn0);
            const float al1 = ex2(mr[f][1] - mn1);
            mr[f][0] = mn0; mr[f][1] = mn1;

            float rs0 = 0.f, rs1 = 0.f;
#pragma unroll
            for (int j = 0; j < 8; ++j) {
                const float p0 = ex2(sacc[f][j][0] - mn0);
                const float p1 = ex2(sacc[f][j][1] - mn0);
                const float p2 = ex2(sacc[f][j][2] - mn1);
                const float p3 = ex2(sacc[f][j][3] - mn1);
                rs0 += p0 + p1;
                rs1 += p2 + p3;
                pa[f][j] = packh2(p0, p1);
                pb[f][j] = packh2(p2, p3);
            }
            rs0 += __shfl_xor_sync(0xffffffffu, rs0, 1);
            rs0 += __shfl_xor_sync(0xffffffffu, rs0, 2);
            rs1 += __shfl_xor_sync(0xffffffffu, rs1, 1);
            rs1 += __shfl_xor_sync(0xffffffffu, rs1, 2);
            lr[f][0] = lr[f][0] * al0 + rs0;
            lr[f][1] = lr[f][1] * al1 + rs1;

#pragma unroll
            for (int j = 0; j < 8; ++j) {
                oacc[f][j][0] *= al0; oacc[f][j][1] *= al0;
                oacc[f][j][2] *= al1; oacc[f][j][3] *= al1;
            }
        }

        // ---- O += P V : one V ldsm feeds 4 MMAs ----
#pragma unroll
        for (int kt = 0; kt < 4; ++kt) {
#pragma unroll
            for (int np = 0; np < 4; ++np) {
                uint32_t b0, b1, b2, b3;
                const uint32_t addr =
                    vs_base[cur] + 2u * (uint32_t)((kt * 16 + vrow) * KST + np * 16 + vcol);
                ldsm_x4_t(b0, b1, b2, b3, addr);
#pragma unroll
                for (int f = 0; f < 2; ++f) {
                    mma16816(oacc[f][2 * np],
                             pa[f][2 * kt], pb[f][2 * kt],
                             pa[f][2 * kt + 1], pb[f][2 * kt + 1], b0, b1);
                    mma16816(oacc[f][2 * np + 1],
                             pa[f][2 * kt], pb[f][2 * kt],
                             pa[f][2 * kt + 1], pb[f][2 * kt + 1], b2, b3);
                }
            }
        }

        __syncthreads();
    }

    // ---- epilogue ----
#pragma unroll
    for (int f = 0; f < 2; ++f) {
        const float inv0 = 1.f / lr[f][0];
        const float inv1 = 1.f / lr[f][1];
        const int rr0 = wrow + f * 16 + g;
        const int rr1 = rr0 + 8;
#pragma unroll
        for (int j = 0; j < 8; ++j) {
            float2 o0 = make_float2(oacc[f][j][0] * inv0, oacc[f][j][1] * inv0);
            float2 o1 = make_float2(oacc[f][j][2] * inv1, oacc[f][j][3] * inv1);
            *(float2*)(Op + (size_t)rr0 * D + j * 8 + 2 * q) = o0;
            *(float2*)(Op + (size_t)rr1 * D + j * 8 + 2 * q) = o1;
        }
    }
}

}  // namespace

extern "C" void kernel_launch(void* const* d_in, const int* /*in_sizes*/, int /*n_in*/,
                              void* d_out, int /*out_size*/) {
    const float* Q = (const float*)d_in[0];
    const float* K = (const float*)d_in[1];
    const float* V = (const float*)d_in[2];
    float* O = (float*)d_out;

    const int n4 = (int)(ELEMS / 4);
    cvt_kv<<<(n4 + 255) / 256, 256>>>(K, V);

    dim3 grid(S / BM, BH);
    fa_fwd<<<grid, 128>>>(Q, O);
}